// round 6
// baseline (speedup 1.0000x reference)
#include <cuda_runtime.h>
#include <cuda_bf16.h>
#include <cstddef>
#include <cstdint>

// Problem constants (CTCLoss_56298431315981): T=1024, B=32, C=1024, L=128
constexpr int kT = 1024;
constexpr int kB = 32;
constexpr int kC = 1024;
constexpr int kL = 128;
constexpr int kS = 2 * kL + 1;   // 257 extended states
constexpr int kRow = 384;        // floats per (b,t) row: 3 comps x 32 lanes x 4
constexpr int kTP = kT + 24;     // padded T: prefetch of t+16 never clamps

// Scratch (static __device__ — no allocations allowed)
// Layout: float4 view [b][t][comp 0..2][lane]; comp2.y = log2(row max prob).
__device__ float g_E2[(size_t)kB * kTP * kRow];
__device__ float g_nll[kB];

// ---- cp.async helpers (async-group completion: no SB-slot aliasing) -------
#define CP_ASYNC16(dst_u32, src_ptr) \
    asm volatile("cp.async.cg.shared.global [%0], [%1], 16;" \
                 :: "r"(dst_u32), "l"(src_ptr) : "memory")
#define CP_COMMIT() asm volatile("cp.async.commit_group;" ::: "memory")
#define CP_WAIT(n)  asm volatile("cp.async.wait_group %0;" :: "n"(n) : "memory")

__device__ __forceinline__ uint32_t smem_u32(const void* p)
{
    uint32_t a;
    asm("{ .reg .u64 t; cvta.to.shared.u64 t, %1; cvt.u32.u64 %0, t; }"
        : "=r"(a) : "l"(p));
    return a;
}

// ---------------------------------------------------------------------------
// 2^d as a product of two representable fp32 powers of two. |d|<=252 exact;
// d<-252 flushes to 0. Factors must stay separate (product can be inf;
// 0 * f1 * f2 must remain 0 for empty-lane halos).
// ---------------------------------------------------------------------------
__device__ __forceinline__ void twoFactor(int d, float& f1, float& f2)
{
    d = max(min(d, 252), -300);
    if (d < -252) { f1 = 0.f; f2 = 0.f; return; }
    const int dh = d / 2;  // trunc toward 0: both halves stay in [-126,126]
    f1 = __int_as_float((dh + 127) << 23);
    f2 = __int_as_float((d - dh + 127) << 23);
}

// ---------------------------------------------------------------------------
// Kernel 1: per-(t,b) softmax; write row-max-normalized linear probabilities
// in lane-major layout, plus log2(rowmax) in comp2.y. One warp per row.
// t-REVERSED block order: small-t rows are written last -> L2-hot for the DP.
// ---------------------------------------------------------------------------
__global__ void __launch_bounds__(256) ctc_emis_kernel(
    const float* __restrict__ data, const int* __restrict__ labels)
{
    __shared__ float sh[8][kC];
    __shared__ int   shlab[8][kL];
    const int warp = threadIdx.x >> 5;
    const int lane = threadIdx.x & 31;
    const int row  = (kT * kB - 1) - ((blockIdx.x << 3) + warp); // reversed
    const int t = row >> 5;                      // B == 32
    const int b = row & 31;

    reinterpret_cast<int4*>(shlab[warp])[lane] =
        reinterpret_cast<const int4*>(labels + b * kL)[lane];

    const float4* src = reinterpret_cast<const float4*>(data + (size_t)(t * kB + b) * kC);

    float m = -3.4e38f;
    float4 v[8];
#pragma unroll
    for (int i = 0; i < 8; i++) {
        v[i] = src[(i << 5) + lane];
        reinterpret_cast<float4*>(sh[warp])[(i << 5) + lane] = v[i];
        m = fmaxf(m, fmaxf(fmaxf(v[i].x, v[i].y), fmaxf(v[i].z, v[i].w)));
    }
#pragma unroll
    for (int o = 16; o; o >>= 1) m = fmaxf(m, __shfl_xor_sync(0xffffffffu, m, o));

    float ssum = 0.f;
#pragma unroll
    for (int i = 0; i < 8; i++) {
        ssum += __expf(v[i].x - m) + __expf(v[i].y - m) +
                __expf(v[i].z - m) + __expf(v[i].w - m);
    }
#pragma unroll
    for (int o = 16; o; o >>= 1) ssum += __shfl_xor_sync(0xffffffffu, ssum, o);

    const float lse = m + __logf(ssum);

    __syncwarp();  // smem stores (data row + labels) visible warp-wide

    const float blank = __expf(sh[warp][0] - lse);   // class 0 = blank
    float out[9];
#pragma unroll
    for (int j = 0; j < 9; j++) out[j] = 0.f;
    const int s0 = 9 * lane;
    float pmax = 0.f;
#pragma unroll
    for (int j = 0; j < 9; j++) {
        const int s = s0 + j;
        if (s < kS) {
            out[j] = (s & 1) ? __expf(sh[warp][shlab[warp][s >> 1]] - lse) : blank;
            pmax = fmaxf(pmax, out[j]);
        }
    }
#pragma unroll
    for (int o = 16; o; o >>= 1) pmax = fmaxf(pmax, __shfl_xor_sync(0xffffffffu, pmax, o));

    const float r   = __frcp_rn(pmax);
    const float lg2 = -__log2f(r);        // log2 of the factor we divided out
#pragma unroll
    for (int j = 0; j < 9; j++) out[j] *= r;

    float4* dst = reinterpret_cast<float4*>(g_E2 + ((size_t)b * kTP + t) * kRow);
    dst[lane]      = make_float4(out[0], out[1], out[2], out[3]);
    dst[32 + lane] = make_float4(out[4], out[5], out[6], out[7]);
    dst[64 + lane] = make_float4(out[8], lg2, 0.f, 0.f);
}

// ---------------------------------------------------------------------------
// Kernel 2: CTC forward DP, linear domain, per-lane block floating point with
// 2-lane frame-gap cap, rescale every 6 steps. One warp per batch element.
// Emission streaming: cp.async -> 16-row smem ring -> register double-buffer.
// No barriers, no MUFU, no local memory, no deep LDG scoreboard.
// ---------------------------------------------------------------------------
__global__ void __launch_bounds__(32) ctc_dp_kernel(
    const int* __restrict__ labels, const int* __restrict__ llen,
    const int* __restrict__ dlen)
{
    __shared__ float ring[16 * kRow];              // 24 KB: 16 emission rows
    const unsigned FULL = 0xffffffffu;
    const int NEGI = -(1 << 28);
    const int b    = blockIdx.x;
    const int lane = threadIdx.x;

    const int len = llen[b];
    const int Tb  = dlen[b];               // 512..1024
    const float* __restrict__ Eb = g_E2 + (size_t)b * kTP * kRow;
    const int* __restrict__ lab  = labels + b * kL;
    const uint32_t rb = smem_u32(ring);

    float allow[9];
#pragma unroll
    for (int j = 0; j < 9; j++) {
        const int s = 9 * lane + j;
        bool al = false;
        if (s < kS && (s & 1) && s >= 3) al = (lab[s >> 1] != lab[(s >> 1) - 1]);
        allow[j] = al ? 1.0f : 0.0f;
    }

    // Prologue: stage rows 1..16 into ring slots (q & 15); one group per row.
#pragma unroll
    for (int q = 1; q <= 16; ++q) {
        const unsigned sa = rb + (unsigned)((q & 15) * (kRow * 4)) + (unsigned)lane * 16;
        const float* gp = Eb + (size_t)q * kRow + lane * 4;
        CP_ASYNC16(sa,        gp);
        CP_ASYNC16(sa + 512,  gp + 128);
        CP_ASYNC16(sa + 1024, gp + 256);
        CP_COMMIT();
    }

    float a[9];
#pragma unroll
    for (int j = 0; j < 9; j++) a[j] = 0.f;
    if (lane == 0) {
        a[0] = __ldg(&Eb[0]);    // t=0 state 0 (blank)
        a[1] = __ldg(&Eb[1]);    // t=0 state 1 (label0)
    }
    float lgsum = __ldg(&Eb[64 * 4 + 1]);  // t=0 row log2(pmax) (comp2 lane0 .y)
    int   X   = 0;
    float sD1 = (lane == 0) ? 0.f : 1.f;   // halo frame factor = sD1*sD2 (keep split!)
    float sD2 = (lane == 0) ? 0.f : 1.f;

    CP_WAIT(14);                            // rows 1,2 arrived
    float4 RA[3], RB[3];
    {
        const float4* sp = reinterpret_cast<const float4*>(ring + 1 * kRow);
        RA[0] = sp[lane]; RA[1] = sp[32 + lane]; RA[2] = sp[64 + lane];
    }

    int t = 1;

    auto dostep = [&](const float4* Pq) {
        float h1 = __shfl_up_sync(FULL, a[8], 1);
        float h2 = __shfl_up_sync(FULL, a[7], 1);
        h1 = (h1 * sD1) * sD2;
        h2 = (h2 * sD1) * sD2;
        lgsum += Pq[2].y;                           // row log2(pmax)
        float na[9];
        na[0] = fmaf(allow[0], h2,   a[0] + h1)   * Pq[0].x;
        na[1] = fmaf(allow[1], h1,   a[1] + a[0]) * Pq[0].y;
        na[2] = fmaf(allow[2], a[0], a[2] + a[1]) * Pq[0].z;
        na[3] = fmaf(allow[3], a[1], a[3] + a[2]) * Pq[0].w;
        na[4] = fmaf(allow[4], a[2], a[4] + a[3]) * Pq[1].x;
        na[5] = fmaf(allow[5], a[3], a[5] + a[4]) * Pq[1].y;
        na[6] = fmaf(allow[6], a[4], a[6] + a[5]) * Pq[1].z;
        na[7] = fmaf(allow[7], a[5], a[7] + a[6]) * Pq[1].w;
        na[8] = fmaf(allow[8], a[6], a[8] + a[7]) * Pq[2].x;
#pragma unroll
        for (int j = 0; j < 9; j++) a[j] = na[j];
    };

    // One full step: prefetch row t+16 (slot t&15, whose old row t was staged
    // to registers at step t-1), wait so row t+1 is ready, stage it into N,
    // compute on C (row t).
    auto step = [&](float4 (&C)[3], float4 (&N)[3]) {
        const unsigned sa = rb + (unsigned)((t & 15) * (kRow * 4)) + (unsigned)lane * 16;
        const float* gp = Eb + (size_t)(t + 16) * kRow + lane * 4;
        CP_ASYNC16(sa,        gp);
        CP_ASYNC16(sa + 512,  gp + 128);
        CP_ASYNC16(sa + 1024, gp + 256);
        CP_COMMIT(); CP_WAIT(14);
        const float4* sp = reinterpret_cast<const float4*>(ring + ((t + 1) & 15) * kRow);
        N[0] = sp[lane]; N[1] = sp[32 + lane]; N[2] = sp[64 + lane];
        dostep(C);
        ++t;
    };

    // Rescale with 2-lane frame cap (alignment propagates 2 lanes/rescale;
    // wavefront moves 12 states = 1.33 lanes per 6-step period).
    auto rescale = [&]() {
        float m = a[0];
#pragma unroll
        for (int j = 1; j < 9; j++) m = fmaxf(m, a[j]);
        const bool nz = (m > 0.f);
        const int  e    = nz ? (((__float_as_int(m) >> 23) & 0xff) - 127) : 0;
        const int  cand = nz ? (X + e) : NEGI;
        const int  c1 = __shfl_up_sync(FULL, cand, 1);
        const int  c2 = __shfl_up_sync(FULL, cand, 2);
        int Xn;
        if (lane == 0) {
            Xn = nz ? cand : X;
        } else {
            const int low  = max(c1 - 24, c2 - 48);
            const int ownc = nz ? cand : NEGI;
            Xn = max(ownc, low);
            if (Xn <= NEGI) Xn = X;                // fully empty region: keep
        }
        float f1, f2;
        twoFactor(X - Xn, f1, f2);                 // rescale own values (split-safe)
#pragma unroll
        for (int j = 0; j < 9; j++) a[j] = (a[j] * f1) * f2;
        X = Xn;
        const int Xp = __shfl_up_sync(FULL, X, 1); // predecessor FINAL frame
        twoFactor(Xp - X, sD1, sD2);
        if (lane == 0) { sD1 = 0.f; sD2 = 0.f; }
    };

    for (; t + 5 < Tb; ) {
        step(RA, RB); step(RB, RA); step(RA, RB);
        step(RB, RA); step(RA, RB); step(RB, RA);
        rescale();
    }
    // Tail (<=5 steps), explicit buffer alternation.
    if (t < Tb) step(RA, RB);
    if (t < Tb) step(RB, RA);
    if (t < Tb) step(RA, RB);
    if (t < Tb) step(RB, RA);
    if (t < Tb) step(RA, RB);

    // Final: combine alpha[2*len] and alpha[2*len-1]; add back row log2 sums.
    __shared__ float Af[288];
    __shared__ int   Xf[32];
#pragma unroll
    for (int j = 0; j < 9; j++) Af[9 * lane + j] = a[j];
    Xf[lane] = X;
    __syncwarp();
    if (lane == 0) {
        const int sB = 2 * len, sL = sB - 1;
        const float aB = Af[sB], aL = Af[sL];
        const float yB = (aB > 0.f) ? (log2f(aB) + (float)Xf[sB / 9]) : -1e30f;
        const float yL = (aL > 0.f) ? (log2f(aL) + (float)Xf[sL / 9]) : -1e30f;
        const float mx = fmaxf(yB, yL);
        const float rr = mx + log2f(exp2f(yB - mx) + exp2f(yL - mx)) + lgsum;
        g_nll[b] = -rr * 0.69314718055994530942f;   // log2 -> ln
    }
}

// ---------------------------------------------------------------------------
// Kernel 3: mean over batch -> d_out[0]. Deterministic (no atomics).
// ---------------------------------------------------------------------------
__global__ void ctc_finish_kernel(float* __restrict__ out)
{
    float v = g_nll[threadIdx.x];
#pragma unroll
    for (int o = 16; o; o >>= 1) v += __shfl_xor_sync(0xffffffffu, v, o);
    if (threadIdx.x == 0) out[0] = v * (1.0f / kB);
}

extern "C" void kernel_launch(void* const* d_in, const int* in_sizes, int n_in,
                              void* d_out, int out_size)
{
    const int*   labels       = (const int*)d_in[0];
    const float* data         = (const float*)d_in[1];
    const int*   label_length = (const int*)d_in[2];
    const int*   data_length  = (const int*)d_in[3];
    float*       out          = (float*)d_out;

    ctc_emis_kernel<<<(kT * kB) / 8, 256>>>(data, labels);
    ctc_dp_kernel<<<kB, 32>>>(labels, label_length, data_length);
    ctc_finish_kernel<<<1, 32>>>(out);
}